// round 7
// baseline (speedup 1.0000x reference)
#include <cuda_runtime.h>

// DEMA decomposition: x (32, 2048, 512) f32 -> (res, ma) each same shape.
//   s0 = x[:,0,:]; b0 = x[:,1,:] - s0
//   s_t = a*x_t + (1-a)*(s_{t-1} + b_{t-1})
//   b_t = be*(s_t - s_{t-1}) + (1-be)*b_{t-1}
//   ma = [s0..s_{T-1}], res = x - ma
//
// Chunked scan: spectral radius sqrt(0.7)~0.837 -> warmup W gives state error
// ~0.837^W. Measured rel_err: W=96 -> 1.1e-7, W=64 -> 1.7e-5, W=48 -> 2-3e-4.
//
// R5: R2 config (the 5.81 TB/s pump champion: CHUNK=64, PLAIN loads, __stcs
// stores, occ ~40%) -- R3/R4 proved __ldcs load hints collapse the pump
// (5.81->5.21 at occ40, 5.48->3.49 at occ20), so no load hints anywhere.
// R2 had nothing saturated (DRAM 73%, issue 18%) => latency/MLP-bound.
// Changes vs R2:
//   1. W 64->48 (error margin 3-4x): warmup traffic 124->93 MB.
//   2. Software-pipelined main loop (depth 8: prefetch 4 while processing 4)
//      + unroll-8 warmup: doubles in-flight bytes/warp to raise the pump.

#define ALPHA 0.3f
#define BETA  0.3f

#define BDIM 32
#define TDIM 2048
#define FDIM 512

#define CHUNK 64
#define WARM  48
#define NCHUNK (TDIM / CHUNK)   // 32
#define F4    (FDIM / 4)        // 128

__device__ __forceinline__ void dema_step(float4& s, float4& bb, const float4 xt) {
    float4 sn;
    sn.x = fmaf(1.0f - ALPHA, s.x + bb.x, ALPHA * xt.x);
    sn.y = fmaf(1.0f - ALPHA, s.y + bb.y, ALPHA * xt.y);
    sn.z = fmaf(1.0f - ALPHA, s.z + bb.z, ALPHA * xt.z);
    sn.w = fmaf(1.0f - ALPHA, s.w + bb.w, ALPHA * xt.w);
    bb.x = fmaf(BETA, sn.x - s.x, (1.0f - BETA) * bb.x);
    bb.y = fmaf(BETA, sn.y - s.y, (1.0f - BETA) * bb.y);
    bb.z = fmaf(BETA, sn.z - s.z, (1.0f - BETA) * bb.z);
    bb.w = fmaf(BETA, sn.w - s.w, (1.0f - BETA) * bb.w);
    s = sn;
}

__global__ void __launch_bounds__(F4, 8) dema_kernel(
    const float* __restrict__ x, float* __restrict__ out)
{
    const int c  = blockIdx.x;      // chunk 0..31
    const int b  = blockIdx.y;      // batch 0..31
    const int f4 = threadIdx.x;     // 0..127

    const float4* __restrict__ xb =
        reinterpret_cast<const float4*>(x + (size_t)b * TDIM * FDIM) + f4;
    float4* __restrict__ res =
        reinterpret_cast<float4*>(out) + (size_t)b * TDIM * F4 + f4;
    float4* __restrict__ ma =
        reinterpret_cast<float4*>(out + (size_t)BDIM * TDIM * FDIM)
        + (size_t)b * TDIM * F4 + f4;

    const int t0 = c * CHUNK;
    float4 s, bb;
    int t;

    if (c == 0) {
        // Exact init
        float4 x0 = xb[0];
        float4 x1 = xb[F4];
        s = x0;
        bb.x = x1.x - x0.x; bb.y = x1.y - x0.y;
        bb.z = x1.z - x0.z; bb.w = x1.w - x0.w;
        __stcs(&ma[0], s);
        __stcs(&res[0], make_float4(0.0f, 0.0f, 0.0f, 0.0f));
        t = 1;
    } else {
        // Warmup: plain loads (no hints!), deep unroll for MLP.
        const int tw = t0 - WARM;
        float4 x0 = xb[tw * F4];
        float4 x1 = xb[(tw + 1) * F4];
        s = x0;
        bb.x = x1.x - x0.x; bb.y = x1.y - x0.y;
        bb.z = x1.z - x0.z; bb.w = x1.w - x0.w;
        #pragma unroll 8
        for (int tt = tw + 1; tt < t0; ++tt) {
            float4 xt = xb[tt * F4];
            dema_step(s, bb, xt);
        }
        t = t0;
    }

    // Main pass: software-pipelined, depth 8 (4 in flight + 4 processing).
    const int tend = t0 + CHUNK;
    float4 p[4];
    #pragma unroll
    for (int i = 0; i < 4; ++i) {
        int ti = t + i; ti = ti < TDIM - 1 ? ti : TDIM - 1;
        p[i] = xb[ti * F4];
    }
    for (; t < tend; t += 4) {
        float4 n[4];
        #pragma unroll
        for (int i = 0; i < 4; ++i) {
            int ti = t + 4 + i; ti = ti < TDIM - 1 ? ti : TDIM - 1;
            n[i] = xb[ti * F4];
        }
        #pragma unroll
        for (int i = 0; i < 4; ++i) {
            if (t + i < tend) {
                dema_step(s, bb, p[i]);
                __stcs(&ma[(t + i) * F4], s);
                float4 r;
                r.x = p[i].x - s.x; r.y = p[i].y - s.y;
                r.z = p[i].z - s.z; r.w = p[i].w - s.w;
                __stcs(&res[(t + i) * F4], r);
            }
        }
        #pragma unroll
        for (int i = 0; i < 4; ++i) p[i] = n[i];
    }
}

extern "C" void kernel_launch(void* const* d_in, const int* in_sizes, int n_in,
                              void* d_out, int out_size)
{
    const float* x = (const float*)d_in[0];
    float* out = (float*)d_out;
    dim3 grid(NCHUNK, BDIM);
    dema_kernel<<<grid, F4>>>(x, out);
}

// round 8
// speedup vs baseline: 1.0173x; 1.0173x over previous
#include <cuda_runtime.h>

// DEMA decomposition: x (32, 2048, 512) f32 -> (res, ma) each same shape.
//   s0 = x[:,0,:]; b0 = x[:,1,:] - s0
//   s_t = a*x_t + (1-a)*(s_{t-1} + b_{t-1})
//   b_t = be*(s_t - s_{t-1}) + (1-be)*b_{t-1}
//   ma = [s0..s_{T-1}], res = x - ma
//
// Chunked scan: spectral radius sqrt(0.7)~0.837 -> warmup W gives state error
// ~0.837^W. Measured rel_err: W=96 -> 1.1e-7, W=64 -> 1.7e-5, W=48 -> 2.9e-4.
//
// R8 config, from cross-round evidence:
//  - CHUNK=64, WARM=48 (R5's traffic win: ~448 MB DRAM).
//  - Simple unroll-4 main loop (R2's 5.81 TB/s pump; R5's software pipeline
//    dropped pump to 5.59 -- pump is a mixed-stream ceiling, not latency).
//  - Plain loads everywhere (R3/R4: __ldcs collapses the pump), __stcs stores.
//  - State reformulation (s, u=s+b):
//        s' = 0.3*x + 0.7*u
//        u' = 1.3*s' + (0.7*u - s)    [b = u - s implied]
//    Dependent chain = 2 FMA (8 cyc) vs ~16 cyc; ~30% fewer flops; init u0=x1.

#define ALPHA 0.3f
#define BETA  0.3f

#define BDIM 32
#define TDIM 2048
#define FDIM 512

#define CHUNK 64
#define WARM  48
#define NCHUNK (TDIM / CHUNK)   // 32
#define F4    (FDIM / 4)        // 128

// (s,u) step: s' = ALPHA*x + (1-ALPHA)*u
//             u' = s' + b' ; b' = BETA*(s'-s) + (1-BETA)*(u-s)
//                => u' = (1+BETA)*s' + ((1-BETA)*u - s)
__device__ __forceinline__ void dema_step(float4& s, float4& u, const float4 xt) {
    float4 sn, tmp;
    // tmp = (1-BETA)*u - s   (independent of sn -> issues in parallel)
    tmp.x = fmaf(1.0f - BETA, u.x, -s.x);
    tmp.y = fmaf(1.0f - BETA, u.y, -s.y);
    tmp.z = fmaf(1.0f - BETA, u.z, -s.z);
    tmp.w = fmaf(1.0f - BETA, u.w, -s.w);
    // sn = ALPHA*x + (1-ALPHA)*u
    sn.x = fmaf(1.0f - ALPHA, u.x, ALPHA * xt.x);
    sn.y = fmaf(1.0f - ALPHA, u.y, ALPHA * xt.y);
    sn.z = fmaf(1.0f - ALPHA, u.z, ALPHA * xt.z);
    sn.w = fmaf(1.0f - ALPHA, u.w, ALPHA * xt.w);
    // u' = (1+BETA)*sn + tmp
    u.x = fmaf(1.0f + BETA, sn.x, tmp.x);
    u.y = fmaf(1.0f + BETA, sn.y, tmp.y);
    u.z = fmaf(1.0f + BETA, sn.z, tmp.z);
    u.w = fmaf(1.0f + BETA, sn.w, tmp.w);
    s = sn;
}

__global__ void __launch_bounds__(F4, 8) dema_kernel(
    const float* __restrict__ x, float* __restrict__ out)
{
    const int c  = blockIdx.x;      // chunk 0..31
    const int b  = blockIdx.y;      // batch 0..31
    const int f4 = threadIdx.x;     // 0..127

    const float4* __restrict__ xb =
        reinterpret_cast<const float4*>(x + (size_t)b * TDIM * FDIM) + f4;
    float4* __restrict__ res =
        reinterpret_cast<float4*>(out) + (size_t)b * TDIM * F4 + f4;
    float4* __restrict__ ma =
        reinterpret_cast<float4*>(out + (size_t)BDIM * TDIM * FDIM)
        + (size_t)b * TDIM * F4 + f4;

    const int t0 = c * CHUNK;
    float4 s, u;   // u = s + b
    int t;

    if (c == 0) {
        // Exact init: s0 = x0, u0 = s0 + (x1 - x0) = x1
        float4 x0 = xb[0];
        float4 x1 = xb[F4];
        s = x0;
        u = x1;
        __stcs(&ma[0], s);
        __stcs(&res[0], make_float4(0.0f, 0.0f, 0.0f, 0.0f));
        t = 1;
    } else {
        // Warmup: pure compute, plain loads, deep unroll.
        const int tw = t0 - WARM;
        float4 x0 = xb[tw * F4];
        float4 x1 = xb[(tw + 1) * F4];
        s = x0;
        u = x1;
        #pragma unroll 8
        for (int tt = tw + 1; tt < t0; ++tt) {
            float4 xt = xb[tt * F4];
            dema_step(s, u, xt);
        }
        t = t0;
    }

    // Main pass: simple unroll-4 loop (best measured pump shape).
    const int tend = t0 + CHUNK;
    #pragma unroll 4
    for (; t < tend; ++t) {
        float4 xt = xb[t * F4];
        dema_step(s, u, xt);
        __stcs(&ma[t * F4], s);
        float4 r;
        r.x = xt.x - s.x; r.y = xt.y - s.y;
        r.z = xt.z - s.z; r.w = xt.w - s.w;
        __stcs(&res[t * F4], r);
    }
}

extern "C" void kernel_launch(void* const* d_in, const int* in_sizes, int n_in,
                              void* d_out, int out_size)
{
    const float* x = (const float*)d_in[0];
    float* out = (float*)d_out;
    dim3 grid(NCHUNK, BDIM);
    dema_kernel<<<grid, F4>>>(x, out);
}